// round 9
// baseline (speedup 1.0000x reference)
#include <cuda_runtime.h>
#include <cuda_bf16.h>
#include <cstdint>

#define N_NODES 40000
#define N_EDGES 640000
#define DIM 128

// bf16 smem strides (in halves): row length 128 + 8 pad
#define HST 136
// dynamic smem layout (half indices)
#define SA_HI 0
#define SA_LO (64 * HST)
#define SW_HI (2 * 64 * HST)
#define SW_LO (2 * 64 * HST + 128 * HST)
#define SMEM_HALVES (2 * 64 * HST + 2 * 128 * HST)   // 52224 halves = 104448 B

// Scratch (no cudaMalloc allowed)
__device__ float g_agg[N_NODES * DIM];
__device__ float g_h[N_NODES * DIM];
__device__ float g_colsum[DIM];
__device__ float g_colsumsq[DIM];

// ---------------------------------------------------------------------------
// K0: zero g_agg + BN stat accumulators
// ---------------------------------------------------------------------------
__global__ void k0z() {
    const int total = N_NODES * DIM / 4;
    float4 z = {0.f, 0.f, 0.f, 0.f};
    for (int idx = blockIdx.x * blockDim.x + threadIdx.x; idx < total;
         idx += gridDim.x * blockDim.x)
        ((float4*)g_agg)[idx] = z;
    if (blockIdx.x == 0 && threadIdx.x < DIM) {
        g_colsum[threadIdx.x]   = 0.0f;
        g_colsumsq[threadIdx.x] = 0.0f;
    }
}

// ---------------------------------------------------------------------------
// K1: edge scatter — one warp per edge, red.global.add.v4.f32 (proven)
// ---------------------------------------------------------------------------
__global__ void k1_scatter(const float* __restrict__ x,
                           const int* __restrict__ ei) {
    int warp = (blockIdx.x * blockDim.x + threadIdx.x) >> 5;
    int lane = threadIdx.x & 31;
    if (warp >= N_EDGES) return;
    int src = __ldg(&ei[warp]);
    int dst = __ldg(&ei[N_EDGES + warp]);
    float4 v = __ldg((const float4*)x + src * (DIM / 4) + lane);
    float* dp = g_agg + (size_t)dst * DIM + lane * 4;
    asm volatile("red.global.add.v4.f32 [%0], {%1, %2, %3, %4};"
                 :: "l"(dp), "f"(v.x), "f"(v.y), "f"(v.z), "f"(v.w)
                 : "memory");
}

// ---------------- bf16 split + mma.sync helpers ----------------
__device__ __forceinline__ void split2(float a, float b, uint32_t& hi, uint32_t& lo) {
    __nv_bfloat162 h = __floats2bfloat162_rn(a, b);
    float ra = a - __bfloat162float(h.x);
    float rb = b - __bfloat162float(h.y);
    __nv_bfloat162 l = __floats2bfloat162_rn(ra, rb);
    hi = *reinterpret_cast<uint32_t*>(&h);
    lo = *reinterpret_cast<uint32_t*>(&l);
}

__device__ __forceinline__ void mma16816(float* d, const uint32_t* a, uint32_t b0, uint32_t b1) {
    asm volatile(
        "mma.sync.aligned.m16n8k16.row.col.f32.bf16.bf16.f32 "
        "{%0,%1,%2,%3}, {%4,%5,%6,%7}, {%8,%9}, {%0,%1,%2,%3};"
        : "+f"(d[0]), "+f"(d[1]), "+f"(d[2]), "+f"(d[3])
        : "r"(a[0]), "r"(a[1]), "r"(a[2]), "r"(a[3]), "r"(b0), "r"(b1));
}

// ---------------------------------------------------------------------------
// K2: h = ((1+eps)x + agg) @ W^T via mma.sync bf16 3-term split (HMMA fallback).
//     Bias omitted (cancels exactly inside BatchNorm). Fused BN sum/sumsq.
//     CTA 256 thr, tile 64 rows x 128 cols, K=128 staged once as bf16 hi/lo.
//     Warp grid 4m x 2n: warp tile 16 rows x 64 cols (8 n-atoms of m16n8k16).
// ---------------------------------------------------------------------------
extern __shared__ __nv_bfloat16 k2h[];

__global__ void __launch_bounds__(256, 2)
k2_gemm(const float* __restrict__ x, const float* __restrict__ Wm,
        const float* __restrict__ gin_eps) {
    __shared__ float cs[DIM], cs2[DIM];

    const int tid  = threadIdx.x;
    const int row0 = blockIdx.x * 64;            // 625 * 64 == 40000 exactly
    const float ce = 1.0f + __ldg(gin_eps);

    if (tid < DIM) { cs[tid] = 0.0f; cs2[tid] = 0.0f; }

    // ---- Stage A = (1+eps)*x + agg  -> bf16 hi/lo, rows 0..63, k 0..127 ----
    for (int i = tid; i < 64 * 32; i += 256) {
        int r = i >> 5, q = i & 31;              // q = float4 column
        size_t off = (size_t)(row0 + r) * 32 + q;
        float4 xv = __ldg((const float4*)x + off);
        float4 gv = *((const float4*)g_agg + off);
        float v0 = fmaf(ce, xv.x, gv.x), v1 = fmaf(ce, xv.y, gv.y);
        float v2 = fmaf(ce, xv.z, gv.z), v3 = fmaf(ce, xv.w, gv.w);
        uint2 hu, lu;
        split2(v0, v1, hu.x, lu.x);
        split2(v2, v3, hu.y, lu.y);
        int hidx = r * HST + q * 4;              // half index
        *reinterpret_cast<uint2*>(k2h + SA_HI + hidx) = hu;
        *reinterpret_cast<uint2*>(k2h + SA_LO + hidx) = lu;
    }
    // ---- Stage W -> bf16 hi/lo, rows n=0..127, k 0..127 ----
    for (int i = tid; i < 128 * 32; i += 256) {
        int n = i >> 5, q = i & 31;
        float4 w = __ldg((const float4*)Wm + (size_t)n * 32 + q);
        uint2 hu, lu;
        split2(w.x, w.y, hu.x, lu.x);
        split2(w.z, w.w, hu.y, lu.y);
        int hidx = n * HST + q * 4;
        *reinterpret_cast<uint2*>(k2h + SW_HI + hidx) = hu;
        *reinterpret_cast<uint2*>(k2h + SW_LO + hidx) = lu;
    }
    __syncthreads();

    const int wid = tid >> 5, lane = tid & 31;
    const int gid = lane >> 2, tg = lane & 3;
    const int wm = wid & 3;          // m-atom: rows wm*16
    const int wn = wid >> 2;         // n-half: cols wn*64

    float d[8][4];
#pragma unroll
    for (int na = 0; na < 8; na++)
#pragma unroll
        for (int c = 0; c < 4; c++) d[na][c] = 0.0f;

    // half-index bases (even -> 4B aligned b32 loads; conflict-free: gid*4+tg spans 32 banks)
    const int aw0 = (wm * 16 + gid) * HST + tg * 2;
    const int bw0 = (wn * 64 + gid) * HST + tg * 2;

#pragma unroll 1
    for (int term = 0; term < 3; term++) {
        const __nv_bfloat16* pA = k2h + ((term == 1) ? SA_LO : SA_HI);
        const __nv_bfloat16* pW = k2h + ((term == 2) ? SW_LO : SW_HI);
#pragma unroll
        for (int ks = 0; ks < 8; ks++) {
            const int ko = ks * 16;
            uint32_t a[4];
            a[0] = *reinterpret_cast<const uint32_t*>(pA + aw0 + ko);
            a[1] = *reinterpret_cast<const uint32_t*>(pA + aw0 + 8 * HST + ko);
            a[2] = *reinterpret_cast<const uint32_t*>(pA + aw0 + ko + 8);
            a[3] = *reinterpret_cast<const uint32_t*>(pA + aw0 + 8 * HST + ko + 8);
#pragma unroll
            for (int na = 0; na < 8; na++) {
                uint32_t b0 = *reinterpret_cast<const uint32_t*>(pW + bw0 + na * 8 * HST + ko);
                uint32_t b1 = *reinterpret_cast<const uint32_t*>(pW + bw0 + na * 8 * HST + ko + 8);
                mma16816(d[na], a, b0, b1);
            }
        }
    }

    // ---- Epilogue: store h + BN partial sums ----
    const int rt_ = row0 + wm * 16 + gid;
    const int rb_ = rt_ + 8;
#pragma unroll
    for (int na = 0; na < 8; na++) {
        int col = wn * 64 + na * 8 + tg * 2;
        float2 t0 = {d[na][0], d[na][1]};
        float2 t1 = {d[na][2], d[na][3]};
        *reinterpret_cast<float2*>(&g_h[(size_t)rt_ * DIM + col]) = t0;
        *reinterpret_cast<float2*>(&g_h[(size_t)rb_ * DIM + col]) = t1;
        atomicAdd(&cs[col],      d[na][0] + d[na][2]);
        atomicAdd(&cs[col + 1],  d[na][1] + d[na][3]);
        atomicAdd(&cs2[col],     d[na][0] * d[na][0] + d[na][2] * d[na][2]);
        atomicAdd(&cs2[col + 1], d[na][1] * d[na][1] + d[na][3] * d[na][3]);
    }
    __syncthreads();
    if (tid < DIM) {
        atomicAdd(&g_colsum[tid],   cs[tid]);
        atomicAdd(&g_colsumsq[tid], cs2[tid]);
    }
}

// ---------------------------------------------------------------------------
// K3: out = relu(gamma*(h-mean)*rsqrt(var+eps)+beta) + x
// ---------------------------------------------------------------------------
__global__ void k3_final(const float* __restrict__ x,
                         const float* __restrict__ gamma,
                         const float* __restrict__ beta,
                         float* __restrict__ out) {
    __shared__ float sc_s[DIM], sh_s[DIM];
    if (threadIdx.x < DIM) {
        int c = threadIdx.x;
        const float invN = 1.0f / (float)N_NODES;
        float mean = g_colsum[c] * invN;
        float var  = g_colsumsq[c] * invN - mean * mean;
        float inv  = rsqrtf(var + 1e-5f);
        float sc   = __ldg(&gamma[c]) * inv;
        sc_s[c] = sc;
        sh_s[c] = __ldg(&beta[c]) - mean * sc;
    }
    __syncthreads();
    const int total = N_NODES * DIM / 4;
    for (int idx = blockIdx.x * blockDim.x + threadIdx.x; idx < total;
         idx += gridDim.x * blockDim.x) {
        int c4 = (idx & 31) << 2;
        float4 h  = ((const float4*)g_h)[idx];
        float4 xv = __ldg((const float4*)x + idx);
        float4 sc = *(float4*)&sc_s[c4];
        float4 sh = *(float4*)&sh_s[c4];
        float4 o;
        o.x = fmaxf(fmaf(h.x, sc.x, sh.x), 0.0f) + xv.x;
        o.y = fmaxf(fmaf(h.y, sc.y, sh.y), 0.0f) + xv.y;
        o.z = fmaxf(fmaf(h.z, sc.z, sh.z), 0.0f) + xv.z;
        o.w = fmaxf(fmaf(h.w, sc.w, sh.w), 0.0f) + xv.w;
        ((float4*)out)[idx] = o;
    }
}

// ---------------------------------------------------------------------------
extern "C" void kernel_launch(void* const* d_in, const int* in_sizes, int n_in,
                              void* d_out, int out_size) {
    const float* x       = (const float*)d_in[0];
    const int*   ei      = (const int*)d_in[1];
    const float* Wm      = (const float*)d_in[2];
    // d_in[3] = bias: cancels exactly inside BatchNorm -> unused
    const float* gamma   = (const float*)d_in[4];
    const float* beta    = (const float*)d_in[5];
    const float* gin_eps = (const float*)d_in[6];
    float* out = (float*)d_out;

    const int smem_k2 = SMEM_HALVES * (int)sizeof(__nv_bfloat16);  // 104448 B
    cudaFuncSetAttribute(k2_gemm, cudaFuncAttributeMaxDynamicSharedMemorySize, smem_k2);

    k0z<<<1184, 256>>>();
    k1_scatter<<<N_EDGES / 8, 256>>>(x, ei);      // 1 warp per edge
    k2_gemm<<<N_NODES / 64, 256, smem_k2>>>(x, Wm, gin_eps);
    k3_final<<<1184, 256>>>(x, gamma, beta, out);
}